// round 14
// baseline (speedup 1.0000x reference)
#include <cuda_runtime.h>
#include <math.h>
#include <stdint.h>

// ---------------------------------------------------------------------------
// Problem constants
// ---------------------------------------------------------------------------
#define BATCH   4
#define NBOX    30
#define IN_DIM  768
#define POS_DIM 64
#define HDIM    832
#define H1DIM   512
#define H2DIM   512
#define OUT_DIM 768
#define ROWS    120
#define NRG     15              // row groups of 8

#define HW64  4096
#define DIM64 4126
#define HW32  1024
#define DIM32 1054

#define OFF_OBJ  ((size_t)0)
#define OFF_S64  ((size_t)ROWS * OUT_DIM)
#define OFF_S32  (OFF_S64 + (size_t)BATCH * DIM64 * DIM64)

// Block-role layout. bits -> L1 -> pure sims -> L2-hybrids -> L3-hybrids.
// Hybrids do their MLP tile, signal, then store a sim unit so the kernel
// tail is store traffic. Deps always flow lower-bid -> higher-bid; the
// long-lived pure sim blocks delay hybrid dispatch until deps are done.
#define NB_B64   32             // 8 per batch
#define NB_B32   4
#define NB_BITS  (NB_B64 + NB_B32)               // 36
#define NB_L1    120            // 15 rg x 8 col-tiles
#define NB_L2    120
#define NB_L3    180            // 15 rg x 12 col-tiles
#define RB64     ((DIM64 + 31) / 32)             // 129 row-blocks per batch
#define RB32     ((DIM32 + 31) / 32)             // 33
#define NUNITS64 (RB64 * BATCH)                  // 516
#define NUNITS32 (RB32 * BATCH)                  // 132
#define NUNITS   (NUNITS64 + NUNITS32)           // 648
#define NB_PURE  (NUNITS - NB_L2 - NB_L3)        // 348

#define BID_B32  NB_B64                          // 32
#define BID_L1   NB_BITS                         // 36
#define BID_PURE (BID_L1 + NB_L1)                // 156
#define BID_L2H  (BID_PURE + NB_PURE)            // 504
#define BID_L3H  (BID_L2H + NB_L2)               // 624
#define GRID     (BID_L3H + NB_L3)               // 804

#define SMEM_BYTES (8 * HDIM * 4)                // 26624 B: max(A-tile, bits, sRed)

// ---------------------------------------------------------------------------
// Scratch
// ---------------------------------------------------------------------------
__device__ float    g_a1[ROWS * H1DIM];
__device__ float    g_a2[ROWS * H2DIM];
__device__ unsigned g_bits64[BATCH * HW64];
__device__ unsigned g_bits32[BATCH * HW32];
__device__ int      g_c1[NRG];
__device__ int      g_c2[NRG];
__device__ int      g_cb64[BATCH];
__device__ int      g_cb32[BATCH];

__global__ void init_counters()
{
    int t = threadIdx.x;
    if (t < NRG)   { g_c1[t] = 0; g_c2[t] = 0; }
    if (t < BATCH) { g_cb64[t] = 0; g_cb32[t] = 0; }
}

// ---------------------------------------------------------------------------
// Flag protocol (gpu-scope)
// ---------------------------------------------------------------------------
__device__ __forceinline__ void wait_cnt(int* c, int idx, int target)
{
    if (threadIdx.x == 0) {
        while (atomicAdd(&c[idx], 0) < target) __nanosleep(128);
        __threadfence();
    }
    __syncthreads();
}

__device__ __forceinline__ void signal_cnt(int* c, int idx)
{
    __syncthreads();
    if (threadIdx.x == 0) { __threadfence(); atomicAdd(&c[idx], 1); }
}

// ---------------------------------------------------------------------------
// Bits producer: rasterize one slice of one batch's membership masks.
// ---------------------------------------------------------------------------
template<int SIZE>
__device__ void bits_block(int b, int slice, int nslices,
                           const float* __restrict__ boxes,
                           const float* __restrict__ masks,
                           unsigned* __restrict__ gbits, int* flag,
                           int (*s_box)[NBOX], unsigned* s_valid)
{
    constexpr int HW = SIZE * SIZE;
    int t = threadIdx.x;
    if (t == 0) *s_valid = 0u;
    __syncthreads();
    if (t < NBOX) {
        const float* bb = boxes + ((size_t)b * NBOX + t) * 4;
        // boxes*SIZE exact (power-of-2 scale); rintf = round-half-even = jnp.round
        s_box[0][t] = (int)rintf(bb[0] * (float)SIZE);
        s_box[1][t] = (int)rintf(bb[1] * (float)SIZE);
        s_box[2][t] = (int)rintf(bb[2] * (float)SIZE);
        s_box[3][t] = (int)rintf(bb[3] * (float)SIZE);
        if (t < NBOX - 1 && masks[b * NBOX + t] == 1.0f)
            atomicOr(s_valid, 1u << t);
    }
    __syncthreads();
    unsigned vm = *s_valid;

    int chunk = HW / nslices;
    int p0 = slice * chunk;
    for (int p = p0 + t; p < p0 + chunk; p += 256) {
        int y = p / SIZE, x = p - y * SIZE;
        unsigned m = 0u;
#pragma unroll
        for (int n = 0; n < NBOX - 1; n++) {
            bool in = (y >= s_box[1][n]) & (y < s_box[3][n]) &
                      (x >= s_box[0][n]) & (x < s_box[2][n]);
            if (in) m |= (1u << n);
        }
        m &= vm;
        if (m == 0u) m = (1u << (NBOX - 1));
        gbits[(size_t)b * HW + p] = m;
    }
    signal_cnt(flag, b);
}

// ---------------------------------------------------------------------------
// MLP helpers
// ---------------------------------------------------------------------------
__device__ void stage_h(int rg, const float* __restrict__ boxes,
                        const float* __restrict__ masks,
                        const float* __restrict__ pembed,
                        const float* __restrict__ pos_table,
                        const float* __restrict__ null_pos,
                        const float* __restrict__ null_xyxy,
                        char* s_raw)
{
    float* sAf = (float*)s_raw;
    int t = threadIdx.x;
    for (int idx = t; idx < 8 * HDIM; idx += 256) {
        int r = idx / HDIM, k = idx - r * HDIM;
        int row = rg * 8 + r;
        int n = row % NBOX;
        float m  = masks[row];
        float om = 1.0f - m;
        float v;
        if (k < IN_DIM) {
            v = (pembed[(size_t)row * IN_DIM + k] + pos_table[(size_t)n * IN_DIM + k]) * m
                + om * null_pos[k];
        } else {
            int kk = k - IN_DIM;
            int fi = kk >> 3, c8 = kk & 7, coord = c8 & 3;
            float freq = powf(100.0f, (float)fi * 0.125f);
            float arg  = boxes[(size_t)row * 4 + coord] * freq;
            float e    = (c8 < 4) ? sinf(arg) : cosf(arg);
            v = e * m + om * null_xyxy[kk];
        }
        sAf[r * HDIM + k] = v;
    }
    __syncthreads();
}

template<int K>
__device__ void stage_A(const float* __restrict__ A, int rg, char* s_raw)
{
    float* sAf = (float*)s_raw;
    int t = threadIdx.x;
    for (int idx = t; idx < 8 * K; idx += 256) {
        int r = idx / K, k = idx - r * K;
        sAf[r * K + k] = __ldcg(&A[(size_t)(rg * 8 + r) * K + k]);   // bypass L1
    }
    __syncthreads();
}

// MLP tile: 8 rows x 64 cols per block, 256 thr = 64 cols x 4 K-slices,
// 8 row-accumulators, double-buffered W prefetch, smem split-K reduction.
template<int K, int NOUT, bool SILU>
__device__ void mlp_compute(const float* __restrict__ W, const float* __restrict__ bias,
                            float* __restrict__ dst, int rg, int cb, char* s_raw)
{
    constexpr int L  = K / 4;
    constexpr int L4 = L / 4;
    const float4* sA = (const float4*)s_raw;     // [8][K/4]

    int t  = threadIdx.x;
    int j  = t & 63;
    int ks = t >> 6;
    int colBase = cb * 64;

    float acc[8];
#pragma unroll
    for (int r = 0; r < 8; r++) acc[r] = 0.f;

    const float* Wp = W + (size_t)(ks * L) * NOUT + colBase + j;
    const int a4base = ks * L4;

    float w0 = __ldg(Wp + (size_t)0 * NOUT);
    float w1 = __ldg(Wp + (size_t)1 * NOUT);
    float w2 = __ldg(Wp + (size_t)2 * NOUT);
    float w3 = __ldg(Wp + (size_t)3 * NOUT);

#pragma unroll 4
    for (int i4 = 0; i4 < L4; i4++) {
        float n0, n1, n2, n3;
        if (i4 + 1 < L4) {
            const float* Wn = Wp + (size_t)((i4 + 1) * 4) * NOUT;
            n0 = __ldg(Wn + (size_t)0 * NOUT);
            n1 = __ldg(Wn + (size_t)1 * NOUT);
            n2 = __ldg(Wn + (size_t)2 * NOUT);
            n3 = __ldg(Wn + (size_t)3 * NOUT);
        }
#pragma unroll
        for (int r = 0; r < 8; r++) {
            float4 a = sA[r * (K / 4) + a4base + i4];
            acc[r] = fmaf(w0, a.x, acc[r]);
            acc[r] = fmaf(w1, a.y, acc[r]);
            acc[r] = fmaf(w2, a.z, acc[r]);
            acc[r] = fmaf(w3, a.w, acc[r]);
        }
        if (i4 + 1 < L4) { w0 = n0; w1 = n1; w2 = n2; w3 = n3; }
    }

    __syncthreads();                             // done reading sA
    float* sRed = (float*)s_raw;                 // [4][8][65] (reuses A storage)
#pragma unroll
    for (int r = 0; r < 8; r++) sRed[(ks * 8 + r) * 65 + j] = acc[r];
    __syncthreads();

    float bj = bias[colBase + j];
#pragma unroll
    for (int rr = 0; rr < 2; rr++) {
        int r = ks * 2 + rr;
        float v = bj;
#pragma unroll
        for (int s = 0; s < 4; s++) v += sRed[(s * 8 + r) * 65 + j];
        if (SILU) v = v / (1.0f + expf(-v));
        dst[(size_t)(rg * 8 + r) * NOUT + colBase + j] = v;
    }
}

// ---------------------------------------------------------------------------
// Sim consumer: wait for batch bits, stage to smem, stream 32 rows.
// Branch-free float4 main loop over the pure sim region + <=32-col scalar
// tail covering the bit strip (and straddle). Zero rows unify via rb=0.
// Default write-back stores (no .cs): let the 126MB L2 buffer the store
// stream and drain in large batches instead of forcing per-line eviction.
// DIM % 4 == 2: even rows body starts at col 0, odd rows at col 2.
// ---------------------------------------------------------------------------
template<int SIZE>
__device__ void sim_block(float* __restrict__ outBase, int b, int rowblk,
                          const unsigned* __restrict__ gbits,
                          int* flag, int target, char* s_raw)
{
    constexpr int HW  = SIZE * SIZE;
    constexpr int DIM = HW + NBOX;
    unsigned* sbits = (unsigned*)s_raw;
    int t = threadIdx.x;

    wait_cnt(flag, b, target);

    {   // stage bits (16 KB max) via uint4 .cg loads
        const uint4* g4 = (const uint4*)(gbits + (size_t)b * HW);
        uint4* s4 = (uint4*)sbits;
        for (int i = t; i < HW / 4; i += 256) s4[i] = __ldcg(&g4[i]);
    }
    __syncthreads();

    const uint2* sb2 = (const uint2*)sbits;
    size_t bbase = (size_t)b * DIM * DIM;

    for (int pi = 0; pi < 32; pi++) {
        int p = rowblk * 32 + pi;
        if (p >= DIM) break;
        float* rowp = outBase + bbase + (size_t)p * DIM;
        int head  = (p & 1) ? 2 : 0;         // odd rows: body starts at col 2
        int pure4 = head ? (HW / 4 - 1) : (HW / 4);   // float4s fully inside [0,HW)
        unsigned rb = (p < HW) ? sbits[p] : 0u;       // rb=0 => all-zero row

        float4* out4 = (float4*)(rowp + head);        // 16B aligned
        const uint2* sb2row = sb2 + (head >> 1);

        if (head && t == 0) {                // odd rows: head cols 0,1 (< HW)
            rowp[0] = (rb & sbits[0]) ? 1.f : 0.f;
            rowp[1] = (rb & sbits[1]) ? 1.f : 0.f;
        }

        // branch-free main loop: cols [head, head + 4*pure4) all < HW
#pragma unroll 4
        for (int i = t; i < pure4; i += 256) {
            uint2 e0 = sb2row[2 * i];
            uint2 e1 = sb2row[2 * i + 1];
            float4 v;
            v.x = (rb & e0.x) ? 1.f : 0.f;
            v.y = (rb & e0.y) ? 1.f : 0.f;
            v.z = (rb & e1.x) ? 1.f : 0.f;
            v.w = (rb & e1.y) ? 1.f : 0.f;
            out4[i] = v;
        }

        // scalar tail: cols [head + 4*pure4, DIM)  (<= 32 columns)
        int c = head + 4 * pure4 + t;
        if (c < DIM) {
            float v = (c < HW) ? ((rb & sbits[c]) ? 1.f : 0.f)
                               : (((rb >> (c - HW)) & 1u) ? 1.f : 0.f);
            rowp[c] = v;
        }
    }
}

// ---------------------------------------------------------------------------
// Sim unit dispatch: units [0,516) = sim64 row-blocks, [516,648) = sim32.
// ---------------------------------------------------------------------------
__device__ void run_sim_unit(int u, float* __restrict__ out, char* s_raw)
{
    if (u < NUNITS64) {
        int b = u / RB64, rb = u - b * RB64;
        sim_block<64>(out + OFF_S64, b, rb, g_bits64, g_cb64, 8, s_raw);
    } else {
        int v = u - NUNITS64;
        int b = v / RB32, rb = v - b * RB32;
        sim_block<32>(out + OFF_S32, b, rb, g_bits32, g_cb32, 1, s_raw);
    }
}

// ---------------------------------------------------------------------------
// Mega kernel — natural regs (NO min-blocks cap: both (256,4) and (256,3)
// caps spilled the MLP inner loop and regressed; regs=105 / 2 blocks/SM is
// the proven optimum).
// ---------------------------------------------------------------------------
__global__ void __launch_bounds__(256)
mega_kernel(const float* __restrict__ boxes, const float* __restrict__ masks,
            const float* __restrict__ pembed, const float* __restrict__ pos_table,
            const float* __restrict__ W1, const float* __restrict__ b1,
            const float* __restrict__ W2, const float* __restrict__ b2,
            const float* __restrict__ W3, const float* __restrict__ b3,
            const float* __restrict__ null_pos, const float* __restrict__ null_xyxy,
            float* __restrict__ out)
{
    __shared__ __align__(16) char s_raw[SMEM_BYTES];
    __shared__ int      s_box[4][NBOX];
    __shared__ unsigned s_valid;

    int bid = blockIdx.x;

    if (bid < BID_B32) {
        int b = bid >> 3, slice = bid & 7;
        bits_block<64>(b, slice, 8, boxes, masks, g_bits64, g_cb64, s_box, &s_valid);
    } else if (bid < BID_L1) {
        int b = bid - BID_B32;
        bits_block<32>(b, 0, 1, boxes, masks, g_bits32, g_cb32, s_box, &s_valid);
    } else if (bid < BID_PURE) {
        int i = bid - BID_L1;
        int rg = i >> 3, cb = i & 7;
        stage_h(rg, boxes, masks, pembed, pos_table, null_pos, null_xyxy, s_raw);
        mlp_compute<HDIM, H1DIM, true>(W1, b1, g_a1, rg, cb, s_raw);
        signal_cnt(g_c1, rg);
    } else if (bid < BID_L2H) {
        // pure sim blocks: units [0, NB_PURE)
        run_sim_unit(bid - BID_PURE, out, s_raw);
    } else if (bid < BID_L3H) {
        // L2 hybrid: MLP tile, signal, then store one sim unit
        int i = bid - BID_L2H;
        int rg = i >> 3, cb = i & 7;
        wait_cnt(g_c1, rg, 8);
        stage_A<H1DIM>(g_a1, rg, s_raw);
        mlp_compute<H1DIM, H2DIM, true>(W2, b2, g_a2, rg, cb, s_raw);
        signal_cnt(g_c2, rg);
        __syncthreads();                      // s_raw reuse: MLP -> bits staging
        run_sim_unit(NB_PURE + i, out, s_raw);
    } else {
        // L3 hybrid: MLP tile -> objs, then store one sim unit (mostly sim32)
        int i = bid - BID_L3H;
        int rg = i / 12, cb = i - rg * 12;
        wait_cnt(g_c2, rg, 8);
        stage_A<H2DIM>(g_a2, rg, s_raw);
        mlp_compute<H2DIM, OUT_DIM, false>(W3, b3, out + OFF_OBJ, rg, cb, s_raw);
        __syncthreads();                      // s_raw reuse
        run_sim_unit(NB_PURE + NB_L2 + i, out, s_raw);
    }
}

// ---------------------------------------------------------------------------
// Launch
// ---------------------------------------------------------------------------
extern "C" void kernel_launch(void* const* d_in, const int* in_sizes, int n_in,
                              void* d_out, int out_size)
{
    const float* boxes      = (const float*)d_in[0];
    const float* masks      = (const float*)d_in[1];
    const float* pembed     = (const float*)d_in[2];
    const float* pos_table  = (const float*)d_in[3];
    const float* W1         = (const float*)d_in[4];
    const float* b1         = (const float*)d_in[5];
    const float* W2         = (const float*)d_in[6];
    const float* b2         = (const float*)d_in[7];
    const float* W3         = (const float*)d_in[8];
    const float* b3         = (const float*)d_in[9];
    const float* null_pos   = (const float*)d_in[10];
    const float* null_xyxy  = (const float*)d_in[11];
    float* out = (float*)d_out;

    init_counters<<<1, 32>>>();
    mega_kernel<<<GRID, 256>>>(boxes, masks, pembed, pos_table,
                               W1, b1, W2, b2, W3, b3,
                               null_pos, null_xyxy, out);
}

// round 15
// speedup vs baseline: 1.3158x; 1.3158x over previous
#include <cuda_runtime.h>
#include <math.h>
#include <stdint.h>

// ---------------------------------------------------------------------------
// Problem constants
// ---------------------------------------------------------------------------
#define BATCH   4
#define NBOX    30
#define IN_DIM  768
#define POS_DIM 64
#define HDIM    832
#define H1DIM   512
#define H2DIM   512
#define OUT_DIM 768
#define ROWS    120
#define NRG     15              // row groups of 8

#define HW64  4096
#define DIM64 4126
#define HW32  1024
#define DIM32 1054

#define OFF_OBJ  ((size_t)0)
#define OFF_S64  ((size_t)ROWS * OUT_DIM)
#define OFF_S32  (OFF_S64 + (size_t)BATCH * DIM64 * DIM64)

// Block-role layout. bits -> L1 -> pure sims (work-stealing) -> L2-hybrids
// -> L3-hybrids. Hybrids do their MLP tile, signal, then store one fixed
// sim unit so the kernel tail is store traffic. Deps flow lower-bid ->
// higher-bid; long-lived pure sims delay hybrid dispatch until deps done.
#define NB_B64   32             // 8 per batch
#define NB_B32   4
#define NB_BITS  (NB_B64 + NB_B32)               // 36
#define NB_L1    120            // 15 rg x 8 col-tiles
#define NB_L2    120
#define NB_L3    180            // 15 rg x 12 col-tiles
#define RB64     ((DIM64 + 31) / 32)             // 129 row-blocks per batch
#define RB32     ((DIM32 + 31) / 32)             // 33
#define NUNITS64 (RB64 * BATCH)                  // 516
#define NUNITS32 (RB32 * BATCH)                  // 132
#define NUNITS   (NUNITS64 + NUNITS32)           // 648
#define NB_PURE  (NUNITS - NB_L2 - NB_L3)        // 348 (units 0..347 stolen)

#define BID_B32  NB_B64                          // 32
#define BID_L1   NB_BITS                         // 36
#define BID_PURE (BID_L1 + NB_L1)                // 156
#define BID_L2H  (BID_PURE + NB_PURE)            // 504
#define BID_L3H  (BID_L2H + NB_L2)               // 624
#define GRID     (BID_L3H + NB_L3)               // 804

#define SMEM_BYTES (8 * HDIM * 4)                // 26624 B: max(A-tile, bits, sRed)

// ---------------------------------------------------------------------------
// Scratch
// ---------------------------------------------------------------------------
__device__ float    g_a1[ROWS * H1DIM];
__device__ float    g_a2[ROWS * H2DIM];
__device__ unsigned g_bits64[BATCH * HW64];
__device__ unsigned g_bits32[BATCH * HW32];
__device__ int      g_c1[NRG];
__device__ int      g_c2[NRG];
__device__ int      g_cb64[BATCH];
__device__ int      g_cb32[BATCH];
__device__ int      g_qpure;                     // work-stealing ticket counter

__global__ void init_counters()
{
    int t = threadIdx.x;
    if (t < NRG)   { g_c1[t] = 0; g_c2[t] = 0; }
    if (t < BATCH) { g_cb64[t] = 0; g_cb32[t] = 0; }
    if (t == 0)    g_qpure = 0;
}

// ---------------------------------------------------------------------------
// Flag protocol (gpu-scope)
// ---------------------------------------------------------------------------
__device__ __forceinline__ void wait_cnt(int* c, int idx, int target)
{
    if (threadIdx.x == 0) {
        while (atomicAdd(&c[idx], 0) < target) __nanosleep(128);
        __threadfence();
    }
    __syncthreads();
}

__device__ __forceinline__ void signal_cnt(int* c, int idx)
{
    __syncthreads();
    if (threadIdx.x == 0) { __threadfence(); atomicAdd(&c[idx], 1); }
}

// ---------------------------------------------------------------------------
// Bits producer: rasterize one slice of one batch's membership masks.
// ---------------------------------------------------------------------------
template<int SIZE>
__device__ void bits_block(int b, int slice, int nslices,
                           const float* __restrict__ boxes,
                           const float* __restrict__ masks,
                           unsigned* __restrict__ gbits, int* flag,
                           int (*s_box)[NBOX], unsigned* s_valid)
{
    constexpr int HW = SIZE * SIZE;
    int t = threadIdx.x;
    if (t == 0) *s_valid = 0u;
    __syncthreads();
    if (t < NBOX) {
        const float* bb = boxes + ((size_t)b * NBOX + t) * 4;
        // boxes*SIZE exact (power-of-2 scale); rintf = round-half-even = jnp.round
        s_box[0][t] = (int)rintf(bb[0] * (float)SIZE);
        s_box[1][t] = (int)rintf(bb[1] * (float)SIZE);
        s_box[2][t] = (int)rintf(bb[2] * (float)SIZE);
        s_box[3][t] = (int)rintf(bb[3] * (float)SIZE);
        if (t < NBOX - 1 && masks[b * NBOX + t] == 1.0f)
            atomicOr(s_valid, 1u << t);
    }
    __syncthreads();
    unsigned vm = *s_valid;

    int chunk = HW / nslices;
    int p0 = slice * chunk;
    for (int p = p0 + t; p < p0 + chunk; p += 256) {
        int y = p / SIZE, x = p - y * SIZE;
        unsigned m = 0u;
#pragma unroll
        for (int n = 0; n < NBOX - 1; n++) {
            bool in = (y >= s_box[1][n]) & (y < s_box[3][n]) &
                      (x >= s_box[0][n]) & (x < s_box[2][n]);
            if (in) m |= (1u << n);
        }
        m &= vm;
        if (m == 0u) m = (1u << (NBOX - 1));
        gbits[(size_t)b * HW + p] = m;
    }
    signal_cnt(flag, b);
}

// ---------------------------------------------------------------------------
// MLP helpers
// ---------------------------------------------------------------------------
__device__ void stage_h(int rg, const float* __restrict__ boxes,
                        const float* __restrict__ masks,
                        const float* __restrict__ pembed,
                        const float* __restrict__ pos_table,
                        const float* __restrict__ null_pos,
                        const float* __restrict__ null_xyxy,
                        char* s_raw)
{
    float* sAf = (float*)s_raw;
    int t = threadIdx.x;
    for (int idx = t; idx < 8 * HDIM; idx += 256) {
        int r = idx / HDIM, k = idx - r * HDIM;
        int row = rg * 8 + r;
        int n = row % NBOX;
        float m  = masks[row];
        float om = 1.0f - m;
        float v;
        if (k < IN_DIM) {
            v = (pembed[(size_t)row * IN_DIM + k] + pos_table[(size_t)n * IN_DIM + k]) * m
                + om * null_pos[k];
        } else {
            int kk = k - IN_DIM;
            int fi = kk >> 3, c8 = kk & 7, coord = c8 & 3;
            float freq = powf(100.0f, (float)fi * 0.125f);
            float arg  = boxes[(size_t)row * 4 + coord] * freq;
            float e    = (c8 < 4) ? sinf(arg) : cosf(arg);
            v = e * m + om * null_xyxy[kk];
        }
        sAf[r * HDIM + k] = v;
    }
    __syncthreads();
}

template<int K>
__device__ void stage_A(const float* __restrict__ A, int rg, char* s_raw)
{
    float* sAf = (float*)s_raw;
    int t = threadIdx.x;
    for (int idx = t; idx < 8 * K; idx += 256) {
        int r = idx / K, k = idx - r * K;
        sAf[r * K + k] = __ldcg(&A[(size_t)(rg * 8 + r) * K + k]);   // bypass L1
    }
    __syncthreads();
}

// MLP tile: 8 rows x 64 cols per block, 256 thr = 64 cols x 4 K-slices,
// 8 row-accumulators, double-buffered W prefetch, smem split-K reduction.
template<int K, int NOUT, bool SILU>
__device__ void mlp_compute(const float* __restrict__ W, const float* __restrict__ bias,
                            float* __restrict__ dst, int rg, int cb, char* s_raw)
{
    constexpr int L  = K / 4;
    constexpr int L4 = L / 4;
    const float4* sA = (const float4*)s_raw;     // [8][K/4]

    int t  = threadIdx.x;
    int j  = t & 63;
    int ks = t >> 6;
    int colBase = cb * 64;

    float acc[8];
#pragma unroll
    for (int r = 0; r < 8; r++) acc[r] = 0.f;

    const float* Wp = W + (size_t)(ks * L) * NOUT + colBase + j;
    const int a4base = ks * L4;

    float w0 = __ldg(Wp + (size_t)0 * NOUT);
    float w1 = __ldg(Wp + (size_t)1 * NOUT);
    float w2 = __ldg(Wp + (size_t)2 * NOUT);
    float w3 = __ldg(Wp + (size_t)3 * NOUT);

#pragma unroll 4
    for (int i4 = 0; i4 < L4; i4++) {
        float n0, n1, n2, n3;
        if (i4 + 1 < L4) {
            const float* Wn = Wp + (size_t)((i4 + 1) * 4) * NOUT;
            n0 = __ldg(Wn + (size_t)0 * NOUT);
            n1 = __ldg(Wn + (size_t)1 * NOUT);
            n2 = __ldg(Wn + (size_t)2 * NOUT);
            n3 = __ldg(Wn + (size_t)3 * NOUT);
        }
#pragma unroll
        for (int r = 0; r < 8; r++) {
            float4 a = sA[r * (K / 4) + a4base + i4];
            acc[r] = fmaf(w0, a.x, acc[r]);
            acc[r] = fmaf(w1, a.y, acc[r]);
            acc[r] = fmaf(w2, a.z, acc[r]);
            acc[r] = fmaf(w3, a.w, acc[r]);
        }
        if (i4 + 1 < L4) { w0 = n0; w1 = n1; w2 = n2; w3 = n3; }
    }

    __syncthreads();                             // done reading sA
    float* sRed = (float*)s_raw;                 // [4][8][65] (reuses A storage)
#pragma unroll
    for (int r = 0; r < 8; r++) sRed[(ks * 8 + r) * 65 + j] = acc[r];
    __syncthreads();

    float bj = bias[colBase + j];
#pragma unroll
    for (int rr = 0; rr < 2; rr++) {
        int r = ks * 2 + rr;
        float v = bj;
#pragma unroll
        for (int s = 0; s < 4; s++) v += sRed[(s * 8 + r) * 65 + j];
        if (SILU) v = v / (1.0f + expf(-v));
        dst[(size_t)(rg * 8 + r) * NOUT + colBase + j] = v;
    }
}

// ---------------------------------------------------------------------------
// Sim consumer, split into staging (cacheable across stolen units of the
// same batch) + row streaming (branch-free float4 .cs main loop + <=32-col
// scalar tail). Zero rows unify via rb=0.
// DIM % 4 == 2: even rows body starts at col 0, odd rows at col 2.
// ---------------------------------------------------------------------------
template<int SIZE>
__device__ void sim_stage(int b, const unsigned* __restrict__ gbits,
                          int* flag, int target, char* s_raw)
{
    constexpr int HW = SIZE * SIZE;
    int t = threadIdx.x;
    wait_cnt(flag, b, target);
    const uint4* g4 = (const uint4*)(gbits + (size_t)b * HW);
    uint4* s4 = (uint4*)s_raw;
    for (int i = t; i < HW / 4; i += 256) s4[i] = __ldcg(&g4[i]);
    __syncthreads();
}

template<int SIZE>
__device__ void sim_rows(float* __restrict__ outBase, int b, int rowblk, char* s_raw)
{
    constexpr int HW  = SIZE * SIZE;
    constexpr int DIM = HW + NBOX;
    unsigned* sbits = (unsigned*)s_raw;
    int t = threadIdx.x;

    const uint2* sb2 = (const uint2*)sbits;
    size_t bbase = (size_t)b * DIM * DIM;

    for (int pi = 0; pi < 32; pi++) {
        int p = rowblk * 32 + pi;
        if (p >= DIM) break;
        float* rowp = outBase + bbase + (size_t)p * DIM;
        int head  = (p & 1) ? 2 : 0;         // odd rows: body starts at col 2
        int pure4 = head ? (HW / 4 - 1) : (HW / 4);   // float4s fully inside [0,HW)
        unsigned rb = (p < HW) ? sbits[p] : 0u;       // rb=0 => all-zero row

        float4* out4 = (float4*)(rowp + head);        // 16B aligned
        const uint2* sb2row = sb2 + (head >> 1);

        if (head && t == 0) {                // odd rows: head cols 0,1 (< HW)
            rowp[0] = (rb & sbits[0]) ? 1.f : 0.f;
            rowp[1] = (rb & sbits[1]) ? 1.f : 0.f;
        }

        // branch-free main loop: cols [head, head + 4*pure4) all < HW
#pragma unroll 4
        for (int i = t; i < pure4; i += 256) {
            uint2 e0 = sb2row[2 * i];
            uint2 e1 = sb2row[2 * i + 1];
            float4 v;
            v.x = (rb & e0.x) ? 1.f : 0.f;
            v.y = (rb & e0.y) ? 1.f : 0.f;
            v.z = (rb & e1.x) ? 1.f : 0.f;
            v.w = (rb & e1.y) ? 1.f : 0.f;
            __stcs(&out4[i], v);
        }

        // scalar tail: cols [head + 4*pure4, DIM)  (<= 32 columns)
        int c = head + 4 * pure4 + t;
        if (c < DIM) {
            float v = (c < HW) ? ((rb & sbits[c]) ? 1.f : 0.f)
                               : (((rb >> (c - HW)) & 1u) ? 1.f : 0.f);
            __stcs(&rowp[c], v);
        }
    }
}

// ---------------------------------------------------------------------------
// Sim unit dispatch with batch-cached staging. key: 0..3 = sim64 batch,
// 4..7 = sim32 batch, -1 = nothing staged.
// Units [0,516) = sim64 row-blocks (b-major), [516,648) = sim32.
// ---------------------------------------------------------------------------
__device__ void run_sim_unit(int u, float* __restrict__ out, char* s_raw, int* key)
{
    if (u < NUNITS64) {
        int b = u / RB64, rb = u - b * RB64;
        if (*key != b) {
            sim_stage<64>(b, g_bits64, g_cb64, 8, s_raw);
            *key = b;
        }
        sim_rows<64>(out + OFF_S64, b, rb, s_raw);
    } else {
        int v = u - NUNITS64;
        int b = v / RB32, rb = v - b * RB32;
        if (*key != 4 + b) {
            sim_stage<32>(b, g_bits32, g_cb32, 1, s_raw);
            *key = 4 + b;
        }
        sim_rows<32>(out + OFF_S32, b, rb, s_raw);
    }
}

// ---------------------------------------------------------------------------
// Mega kernel — natural regs (NO min-blocks cap: (256,4) and (256,3) caps
// both spilled the MLP inner loop and regressed; regs~105 / 2 blocks/SM is
// the proven optimum).
// ---------------------------------------------------------------------------
__global__ void __launch_bounds__(256)
mega_kernel(const float* __restrict__ boxes, const float* __restrict__ masks,
            const float* __restrict__ pembed, const float* __restrict__ pos_table,
            const float* __restrict__ W1, const float* __restrict__ b1,
            const float* __restrict__ W2, const float* __restrict__ b2,
            const float* __restrict__ W3, const float* __restrict__ b3,
            const float* __restrict__ null_pos, const float* __restrict__ null_xyxy,
            float* __restrict__ out)
{
    __shared__ __align__(16) char s_raw[SMEM_BYTES];
    __shared__ int      s_box[4][NBOX];
    __shared__ unsigned s_valid;
    __shared__ int      s_unit;

    int bid = blockIdx.x;

    if (bid < BID_B32) {
        int b = bid >> 3, slice = bid & 7;
        bits_block<64>(b, slice, 8, boxes, masks, g_bits64, g_cb64, s_box, &s_valid);
    } else if (bid < BID_L1) {
        int b = bid - BID_B32;
        bits_block<32>(b, 0, 1, boxes, masks, g_bits32, g_cb32, s_box, &s_valid);
    } else if (bid < BID_PURE) {
        int i = bid - BID_L1;
        int rg = i >> 3, cb = i & 7;
        stage_h(rg, boxes, masks, pembed, pos_table, null_pos, null_xyxy, s_raw);
        mlp_compute<HDIM, H1DIM, true>(W1, b1, g_a1, rg, cb, s_raw);
        signal_cnt(g_c1, rg);
    } else if (bid < BID_L2H) {
        // pure sim blocks: steal units [0, NB_PURE) from the ticket queue.
        int key = -1;
        for (;;) {
            if (threadIdx.x == 0) s_unit = atomicAdd(&g_qpure, 1);
            __syncthreads();
            int u = s_unit;
            __syncthreads();
            if (u >= NB_PURE) break;
            run_sim_unit(u, out, s_raw, &key);
        }
    } else if (bid < BID_L3H) {
        // L2 hybrid: MLP tile, signal, then store one fixed sim unit
        int i = bid - BID_L2H;
        int rg = i >> 3, cb = i & 7;
        wait_cnt(g_c1, rg, 8);
        stage_A<H1DIM>(g_a1, rg, s_raw);
        mlp_compute<H1DIM, H2DIM, true>(W2, b2, g_a2, rg, cb, s_raw);
        signal_cnt(g_c2, rg);
        __syncthreads();                      // s_raw reuse: MLP -> bits staging
        int key = -1;
        run_sim_unit(NB_PURE + i, out, s_raw, &key);
    } else {
        // L3 hybrid: MLP tile -> objs, then store one fixed sim unit
        int i = bid - BID_L3H;
        int rg = i / 12, cb = i - rg * 12;
        wait_cnt(g_c2, rg, 8);
        stage_A<H2DIM>(g_a2, rg, s_raw);
        mlp_compute<H2DIM, OUT_DIM, false>(W3, b3, out + OFF_OBJ, rg, cb, s_raw);
        __syncthreads();                      // s_raw reuse
        int key = -1;
        run_sim_unit(NB_PURE + NB_L2 + i, out, s_raw, &key);
    }
}

// ---------------------------------------------------------------------------
// Launch
// ---------------------------------------------------------------------------
extern "C" void kernel_launch(void* const* d_in, const int* in_sizes, int n_in,
                              void* d_out, int out_size)
{
    const float* boxes      = (const float*)d_in[0];
    const float* masks      = (const float*)d_in[1];
    const float* pembed     = (const float*)d_in[2];
    const float* pos_table  = (const float*)d_in[3];
    const float* W1         = (const float*)d_in[4];
    const float* b1         = (const float*)d_in[5];
    const float* W2         = (const float*)d_in[6];
    const float* b2         = (const float*)d_in[7];
    const float* W3         = (const float*)d_in[8];
    const float* b3         = (const float*)d_in[9];
    const float* null_pos   = (const float*)d_in[10];
    const float* null_xyxy  = (const float*)d_in[11];
    float* out = (float*)d_out;

    init_counters<<<1, 32>>>();
    mega_kernel<<<GRID, 256>>>(boxes, masks, pembed, pos_table,
                               W1, b1, W2, b2, W3, b3,
                               null_pos, null_xyxy, out);
}